// round 2
// baseline (speedup 1.0000x reference)
#include <cuda_runtime.h>

// ---------------- problem constants ----------------
#define B_    1024
#define F_    512
#define H_    1024
#define S_    8
#define BOX_  12
#define MAXB_ 64
#define MAXSY_ 64
#define MAXS_ 16
#define L_    126

// ---------------- GEMM tile config ----------------
#define BM 64
#define BN 64
#define BK 16
#define NTHR 256

// ---------------- device state ----------------
__device__ float g_stack[MAXS_][B_ * F_];    // 32 MB stack planes
__device__ float g_h[B_ * H_];               // hidden activations (stage A output)
__device__ float g_box12[MAXB_][B_ * BOX_];  // box projections, computed at pop time
__device__ float g_sym[MAXSY_][B_ * S_];     // sym outputs, computed at push time

// ---------------- f32x2 helpers (full-rate fp32 FMA on sm_103a) ----------------
__device__ __forceinline__ unsigned long long dup2(float a) {
    unsigned long long r;
    asm("mov.b64 %0, {%1, %1};" : "=l"(r) : "r"(__float_as_uint(a)));
    return r;
}
__device__ __forceinline__ void ffma2(unsigned long long& d,
                                      unsigned long long a, unsigned long long b) {
    asm("fma.rn.f32x2 %0, %1, %2, %0;" : "+l"(d) : "l"(a), "l"(b));
}
__device__ __forceinline__ float2 unpack2(unsigned long long v) {
    float2 r;
    asm("mov.b64 {%0, %1}, %2;" : "=f"(r.x), "=f"(r.y) : "l"(v));
    return r;
}

// ---------------- op-sequence scan (replayed per block; 126 iters, trivial) ----
struct ScanState { int op, sp, bc, sc; };
__device__ __forceinline__ ScanState scan_ops(const int* __restrict__ ops, int t) {
    int sp = 1, bc = 0, sc = 0;
    for (int s = 0; s < t; ++s) {
        int o = ops[L_ - 1 - s];   // processing order = reversed storage order
        sp += (o == 1) - (o == 0);
        bc += (o == 0);
        sc += (o == 2);
    }
    ScanState st;
    st.op = (t < L_) ? ops[L_ - 1 - t] : -1;
    st.sp = sp; st.bc = bc; st.sc = sc;
    return st;
}

// ---------------- fused GEMM tile: C = tanh(A · Wᵀ + bias) -----------------
// A: [1024 x K] row-major (lda=K). W: [N x K] row-major. C row-major (ldc).
// Block computes tile [m0:m0+64) x [n0:n0+64) of the N columns (n0 may exceed N
// partially; guarded). 256 threads, 4x4 per-thread micro-tile, f32x2 accum.
__device__ __forceinline__ void gemm_tile(
    const float* __restrict__ A, const float* __restrict__ W,
    const float* __restrict__ bias, float* __restrict__ C,
    int K, int N, int ldc, int m0, int n0)
{
    __shared__ __align__(16) float As[BK][BM + 4];
    __shared__ __align__(16) float Ws[BK][BN + 4];

    const int tid = threadIdx.x;
    const int lm  = tid / 4;         // 0..63  (row within tile for loads)
    const int lk  = (tid % 4) * 4;   // 0,4,8,12 (k offset for float4 load)
    const int tm0 = (tid % 16) * 4;  // compute micro-tile origin (m)
    const int tn0 = (tid / 16) * 4;  // compute micro-tile origin (n)

    unsigned long long acc[4][2];
#pragma unroll
    for (int i = 0; i < 4; ++i) { acc[i][0] = 0ull; acc[i][1] = 0ull; }

    const float* Aptr = A + (size_t)(m0 + lm) * K + lk;
    const bool wvalid = (n0 + lm) < N;
    const float* Wptr = W + (size_t)(n0 + lm) * K + lk;

    // prefetch first tile
    float4 av = *(const float4*)(Aptr);
    float4 wv = wvalid ? *(const float4*)(Wptr) : make_float4(0.f, 0.f, 0.f, 0.f);

    for (int k0 = 0; k0 < K; k0 += BK) {
        __syncthreads();   // previous compute done reading smem
        As[lk + 0][lm] = av.x; As[lk + 1][lm] = av.y;
        As[lk + 2][lm] = av.z; As[lk + 3][lm] = av.w;
        Ws[lk + 0][lm] = wv.x; Ws[lk + 1][lm] = wv.y;
        Ws[lk + 2][lm] = wv.z; Ws[lk + 3][lm] = wv.w;
        __syncthreads();

        // prefetch next tile while computing this one
        int kn = k0 + BK;
        if (kn < K) {
            av = *(const float4*)(Aptr + kn);
            wv = wvalid ? *(const float4*)(Wptr + kn) : make_float4(0.f, 0.f, 0.f, 0.f);
        }

#pragma unroll
        for (int k = 0; k < BK; ++k) {
            float4 a4 = *(const float4*)&As[k][tm0];
            ulonglong2 bv = *(const ulonglong2*)&Ws[k][tn0];
            unsigned long long a0 = dup2(a4.x), a1 = dup2(a4.y),
                               a2 = dup2(a4.z), a3 = dup2(a4.w);
            ffma2(acc[0][0], a0, bv.x); ffma2(acc[0][1], a0, bv.y);
            ffma2(acc[1][0], a1, bv.x); ffma2(acc[1][1], a1, bv.y);
            ffma2(acc[2][0], a2, bv.x); ffma2(acc[2][1], a2, bv.y);
            ffma2(acc[3][0], a3, bv.x); ffma2(acc[3][1], a3, bv.y);
        }
    }

#pragma unroll
    for (int i = 0; i < 4; ++i) {
        int row = m0 + tm0 + i;
        float* crow = C + (size_t)row * ldc + n0;
#pragma unroll
        for (int j = 0; j < 2; ++j) {
            float2 v = unpack2(acc[i][j]);
            int na = tn0 + 2 * j, nb = na + 1;
            if (n0 + na < N) crow[na] = tanhf(v.x + bias[n0 + na]);
            if (n0 + nb < N) crow[nb] = tanhf(v.y + bias[n0 + nb]);
        }
    }
}

// ---------------- kernels ----------------
__global__ void k_init(const float* __restrict__ x) {
    int i = blockIdx.x * blockDim.x + threadIdx.x;
    if (i < B_ * F_) g_stack[0][i] = x[i];
}

// Stage A: h = tanh(top · Wᵀ + b), W ∈ {Wd (op1), Wsd (op2)}
__global__ __launch_bounds__(NTHR)
void k_stageA(const int* __restrict__ ops, int t,
              const float* __restrict__ Wd, const float* __restrict__ bd,
              const float* __restrict__ Wsd, const float* __restrict__ bsd) {
    __shared__ int s_op, s_sp;
    if (threadIdx.x == 0) { ScanState st = scan_ops(ops, t); s_op = st.op; s_sp = st.sp; }
    __syncthreads();
    int op = s_op;
    if (op != 1 && op != 2) return;
    const float* A = g_stack[s_sp - 1];
    const float* W = (op == 1) ? Wd : Wsd;
    const float* b = (op == 1) ? bd : bsd;
    gemm_tile(A, W, b, g_h, F_, H_, H_, blockIdx.y * BM, blockIdx.x * BN);
}

// Stage B (fused): op1 -> l (cols 0..511 -> stack[sp-1]) and r (cols 512..1023 -> stack[sp]);
//                  op2 -> f (cols 0..511 -> stack[sp-1]) and s (8 cols -> symbuf[sc]).
__global__ __launch_bounds__(NTHR)
void k_stageB(const int* __restrict__ ops, int t,
              const float* __restrict__ Wl, const float* __restrict__ bl,
              const float* __restrict__ Wr, const float* __restrict__ br,
              const float* __restrict__ Wsf, const float* __restrict__ bsf,
              const float* __restrict__ Wss, const float* __restrict__ bss) {
    __shared__ int s_op, s_sp, s_sc;
    if (threadIdx.x == 0) {
        ScanState st = scan_ops(ops, t);
        s_op = st.op; s_sp = st.sp; s_sc = st.sc;
    }
    __syncthreads();
    int op = s_op;
    if (op != 1 && op != 2) return;
    int n0 = blockIdx.x * BN;
    int m0 = blockIdx.y * BM;
    if (op == 1) {
        if (n0 < F_)
            gemm_tile(g_h, Wl, bl, g_stack[s_sp - 1], H_, F_, F_, m0, n0);
        else
            gemm_tile(g_h, Wr, br, g_stack[s_sp], H_, F_, F_, m0, n0 - F_);
    } else { // op == 2
        if (n0 < F_)
            gemm_tile(g_h, Wsf, bsf, g_stack[s_sp - 1], H_, F_, F_, m0, n0);
        else if (n0 == F_)
            gemm_tile(g_h, Wss, bss, g_sym[s_sc], H_, S_, S_, m0, 0);
        // n0 > F_: nothing to do
    }
}

// Pop (op0): project the popped top through the box decoder immediately
// (boxes[j] = tanh(Wbox · feat + bbox)) — avoids a 128MB buffer + final GEMM.
__global__ void k_pop(const int* __restrict__ ops, int t,
                      const float* __restrict__ Wbox, const float* __restrict__ bbox) {
    __shared__ int s_op, s_sp, s_bc;
    __shared__ float sf[F_];
    if (threadIdx.x == 0) {
        ScanState st = scan_ops(ops, t);
        s_op = st.op; s_sp = st.sp; s_bc = st.bc;
    }
    __syncthreads();
    if (s_op != 0) return;
    int b = blockIdx.x;
    const float* top = g_stack[s_sp - 1] + (size_t)b * F_;
    for (int i = threadIdx.x; i < F_; i += blockDim.x) sf[i] = top[i];
    __syncthreads();
    int w = threadIdx.x / 32, lane = threadIdx.x % 32;
    for (int c = w; c < BOX_; c += 4) {
        const float* wr = Wbox + (size_t)c * F_;
        float sum = 0.f;
        for (int i = lane; i < F_; i += 32) sum += sf[i] * wr[i];
#pragma unroll
        for (int off = 16; off > 0; off >>= 1)
            sum += __shfl_down_sync(0xffffffffu, sum, off);
        if (lane == 0)
            g_box12[s_bc][b * BOX_ + c] = tanhf(sum + bbox[c]);
    }
}

// Emit final outputs: boxes [B,64,12] then syms [B,64,8], reversed & zero-padded.
__global__ void k_emit(const int* __restrict__ ops, float* __restrict__ out) {
    __shared__ int s_bc, s_sc;
    if (threadIdx.x == 0) {
        ScanState st = scan_ops(ops, L_);
        s_bc = st.bc; s_sc = st.sc;
    }
    __syncthreads();
    int idx = blockIdx.x * blockDim.x + threadIdx.x;
    const int NBOX = B_ * MAXB_ * BOX_;
    const int NSYM = B_ * MAXSY_ * S_;
    if (idx < NBOX) {
        int b = idx / (MAXB_ * BOX_);
        int r = idx % (MAXB_ * BOX_);
        int j = r / BOX_, c = r % BOX_;
        float v = 0.f;
        if (j < s_bc) v = g_box12[s_bc - 1 - j][b * BOX_ + c];
        out[idx] = v;
    } else if (idx < NBOX + NSYM) {
        int i2 = idx - NBOX;
        int b = i2 / (MAXSY_ * S_);
        int r = i2 % (MAXSY_ * S_);
        int j = r / S_, c = r % S_;
        float v = 0.f;
        if (j < s_sc) v = g_sym[s_sc - 1 - j][b * S_ + c];
        out[NBOX + i2] = v;
    }
}

// ---------------- launch ----------------
extern "C" void kernel_launch(void* const* d_in, const int* in_sizes, int n_in,
                              void* d_out, int out_size) {
    (void)in_sizes; (void)n_in; (void)out_size;
    const float* inputStacks = (const float*)d_in[0];
    const int*   ops  = (const int*)d_in[1];
    const float* Wd   = (const float*)d_in[2];
    const float* bd   = (const float*)d_in[3];
    const float* Wl   = (const float*)d_in[4];
    const float* bl   = (const float*)d_in[5];
    const float* Wr   = (const float*)d_in[6];
    const float* br   = (const float*)d_in[7];
    const float* Wsd  = (const float*)d_in[8];
    const float* bsd  = (const float*)d_in[9];
    const float* Wsf  = (const float*)d_in[10];
    const float* bsf  = (const float*)d_in[11];
    const float* Wss  = (const float*)d_in[12];
    const float* bss  = (const float*)d_in[13];
    const float* Wbox = (const float*)d_in[14];
    const float* bbox = (const float*)d_in[15];

    k_init<<<(B_ * F_ + 255) / 256, 256>>>(inputStacks);

    dim3 gA(H_ / BN, B_ / BM);   // 16 x 16 blocks (N=1024)
    dim3 gB(H_ / BN, B_ / BM);   // 16 x 16 blocks (covers fused 1024 cols)
    for (int t = 0; t < L_; ++t) {
        k_stageA<<<gA, NTHR>>>(ops, t, Wd, bd, Wsd, bsd);
        k_stageB<<<gB, NTHR>>>(ops, t, Wl, bl, Wr, br, Wsf, bsf, Wss, bss);
        k_pop<<<B_, 128>>>(ops, t, Wbox, bbox);
    }

    int total = B_ * MAXB_ * BOX_ + B_ * MAXSY_ * S_;
    k_emit<<<(total + 255) / 256, 256>>>(ops, (float*)d_out);
}

// round 3
// speedup vs baseline: 1.1601x; 1.1601x over previous
#include <cuda_runtime.h>

#define B_ 1024
#define F_ 512
#define H_ 1024
#define S_ 8
#define BOX_ 12
#define MAXB_ 64
#define MAXSY_ 64
#define L_ 126
#define G_ 256
#define NT_ 256
#define BM 64
#define BN 64
#define BK 16

__device__ float g_stack[4][B_ * F_];
__device__ float g_h[B_ * H_];
__device__ float g_box[MAXB_][B_ * BOX_];
__device__ float g_sym[MAXSY_][B_ * S_];
__device__ unsigned g_cnt = 0;
__device__ unsigned g_gen = 0;

typedef unsigned long long u64;

__device__ __forceinline__ u64 dup2(float a) {
    u64 r; asm("mov.b64 %0,{%1,%1};" : "=l"(r) : "r"(__float_as_uint(a))); return r;
}
__device__ __forceinline__ void ffma2(u64& d, u64 a, u64 b) {
    asm("fma.rn.f32x2 %0,%1,%2,%0;" : "+l"(d) : "l"(a), "l"(b));
}
__device__ __forceinline__ float2 unpack2(u64 v) {
    float2 r; asm("mov.b64 {%0,%1},%2;" : "=f"(r.x), "=f"(r.y) : "l"(v)); return r;
}
// tanh(x) = 1 - 2/(e^{2x}+1): exact identity, only MUFU rounding (~1e-6 rel)
__device__ __forceinline__ float fast_tanh(float x) {
    float e, r;
    asm("ex2.approx.f32 %0,%1;" : "=f"(e) : "f"(x * 2.8853900817779268f));
    asm("rcp.approx.f32 %0,%1;" : "=f"(r) : "f"(e + 1.0f));
    return fmaf(-2.0f, r, 1.0f);
}

// grid barrier: all G_ blocks resident (guaranteed by __launch_bounds__(NT_,2))
__device__ __forceinline__ void gsync() {
    __syncthreads();
    if (threadIdx.x == 0) {
        volatile unsigned* gen = &g_gen;
        unsigned g = *gen;
        __threadfence();                      // release my block's writes
        if (atomicAdd(&g_cnt, 1u) == G_ - 1u) {
            g_cnt = 0;
            __threadfence();
            *gen = g + 1u;
        } else {
            while (*gen == g) { __nanosleep(64); }
        }
        __threadfence();                      // acquire (CCTL.IVALL: drop stale L1)
    }
    __syncthreads();
}

// C[m0..m0+64, n0..n0+64) = tanh(A·Wᵀ + bias). A:[MxK], W:[Nv x K] row-major.
__device__ __noinline__ void gemm_tile(
    const float* __restrict__ A, const float* __restrict__ W,
    const float* __restrict__ bias, float* __restrict__ C,
    int K, int Nv, int ldc, int m0, int n0)
{
    __shared__ __align__(16) float As[BK][BM + 4];
    __shared__ __align__(16) float Ws[BK][BN + 4];

    const int tid = threadIdx.x;
    const int lm  = tid >> 2;
    const int lk  = (tid & 3) * 4;
    const int tm0 = (tid & 15) * 4;
    const int tn0 = (tid >> 4) * 4;

    u64 acc[4][2];
#pragma unroll
    for (int i = 0; i < 4; ++i) { acc[i][0] = 0ull; acc[i][1] = 0ull; }

    const float* Aptr = A + (size_t)(m0 + lm) * K + lk;
    const bool wvalid = (n0 + lm) < Nv;
    const float* Wptr = W + (size_t)(n0 + lm) * K + lk;

    float4 av = *(const float4*)(Aptr);
    float4 wv = wvalid ? *(const float4*)(Wptr) : make_float4(0.f, 0.f, 0.f, 0.f);

    for (int k0 = 0; k0 < K; k0 += BK) {
        __syncthreads();
        As[lk + 0][lm] = av.x; As[lk + 1][lm] = av.y;
        As[lk + 2][lm] = av.z; As[lk + 3][lm] = av.w;
        Ws[lk + 0][lm] = wv.x; Ws[lk + 1][lm] = wv.y;
        Ws[lk + 2][lm] = wv.z; Ws[lk + 3][lm] = wv.w;
        __syncthreads();

        int kn = k0 + BK;
        if (kn < K) {
            av = *(const float4*)(Aptr + kn);
            wv = wvalid ? *(const float4*)(Wptr + kn) : make_float4(0.f, 0.f, 0.f, 0.f);
        }
#pragma unroll
        for (int k = 0; k < BK; ++k) {
            float4 a4 = *(const float4*)&As[k][tm0];
            ulonglong2 bv = *(const ulonglong2*)&Ws[k][tn0];
            u64 a0 = dup2(a4.x), a1 = dup2(a4.y), a2 = dup2(a4.z), a3 = dup2(a4.w);
            ffma2(acc[0][0], a0, bv.x); ffma2(acc[0][1], a0, bv.y);
            ffma2(acc[1][0], a1, bv.x); ffma2(acc[1][1], a1, bv.y);
            ffma2(acc[2][0], a2, bv.x); ffma2(acc[2][1], a2, bv.y);
            ffma2(acc[3][0], a3, bv.x); ffma2(acc[3][1], a3, bv.y);
        }
    }
#pragma unroll
    for (int i = 0; i < 4; ++i) {
        float* crow = C + (size_t)(m0 + tm0 + i) * ldc + n0;
#pragma unroll
        for (int j = 0; j < 2; ++j) {
            float2 v = unpack2(acc[i][j]);
            int na = tn0 + 2 * j, nb = na + 1;
            if (n0 + na < Nv) crow[na] = fast_tanh(v.x + __ldg(&bias[n0 + na]));
            if (n0 + nb < Nv) crow[nb] = fast_tanh(v.y + __ldg(&bias[n0 + nb]));
        }
    }
}

__global__ __launch_bounds__(NT_, 2)
void k_persist(const float* __restrict__ x, const int* __restrict__ ops,
               const float* __restrict__ Wd,  const float* __restrict__ bd,
               const float* __restrict__ Wl,  const float* __restrict__ bl,
               const float* __restrict__ Wr,  const float* __restrict__ br,
               const float* __restrict__ Wsd, const float* __restrict__ bsd,
               const float* __restrict__ Wsf, const float* __restrict__ bsf,
               const float* __restrict__ Wss, const float* __restrict__ bss,
               const float* __restrict__ Wbox,const float* __restrict__ bbox,
               float* __restrict__ out)
{
    const int id = blockIdx.x;
    for (int i = id * NT_ + threadIdx.x; i < B_ * F_; i += G_ * NT_)
        g_stack[0][i] = x[i];
    gsync();

    int sp = 1, bc = 0, sc = 0;
    for (int t = 0; t < L_; ++t) {
        const int op = __ldg(&ops[L_ - 1 - t]);   // processing order (row 0)
        if (op == 1) {
            gemm_tile(g_stack[sp - 1], Wd, bd, g_h, F_, H_, H_,
                      (id >> 4) * BM, (id & 15) * BN);
            gsync();
            if (id < 128)
                gemm_tile(g_h, Wl, bl, g_stack[sp - 1], H_, F_, F_,
                          (id >> 3) * BM, (id & 7) * BN);
            else
                gemm_tile(g_h, Wr, br, g_stack[sp], H_, F_, F_,
                          ((id - 128) >> 3) * BM, ((id - 128) & 7) * BN);
            gsync();
            ++sp;
        } else if (op == 2) {
            gemm_tile(g_stack[sp - 1], Wsd, bsd, g_h, F_, H_, H_,
                      (id >> 4) * BM, (id & 15) * BN);
            gsync();
            if (id < 128)
                gemm_tile(g_h, Wsf, bsf, g_stack[sp - 1], H_, F_, F_,
                          (id >> 3) * BM, (id & 7) * BN);
            else if (id < 144)
                gemm_tile(g_h, Wss, bss, g_sym[sc], H_, S_, S_,
                          (id - 128) * BM, 0);
            gsync();
            ++sc;
        } else {
            // pop: box[bc] = tanh(Wbox·top + bbox). 8 warps: 2 warps/row, 4 rows/block.
            const int w = threadIdx.x >> 5, lane = threadIdx.x & 31;
            const int row = id * 4 + (w >> 1);
            const float* tr = g_stack[sp - 1] + (size_t)row * F_;
            float xv[F_ / 32];
#pragma unroll
            for (int i = 0; i < F_ / 32; ++i) xv[i] = tr[lane + 32 * i];
            for (int c = (w & 1); c < BOX_; c += 2) {
                const float* wr = Wbox + (size_t)c * F_;
                float s = 0.f;
#pragma unroll
                for (int i = 0; i < F_ / 32; ++i)
                    s = fmaf(xv[i], __ldg(&wr[lane + 32 * i]), s);
#pragma unroll
                for (int off = 16; off > 0; off >>= 1)
                    s += __shfl_xor_sync(0xffffffffu, s, off);
                if (lane == 0)
                    g_box[bc][row * BOX_ + c] = fast_tanh(s + __ldg(&bbox[c]));
            }
            ++bc; --sp;   // no barrier needed: next phase's gsync orders everything
        }
    }
    gsync();

    // emit: boxes [B,64,12] then syms [B,64,8], reversed + zero-padded
    const int NBOX = B_ * MAXB_ * BOX_;
    const int NSYM = B_ * MAXSY_ * S_;
    for (int idx = id * NT_ + threadIdx.x; idx < NBOX + NSYM; idx += G_ * NT_) {
        if (idx < NBOX) {
            int b = idx / (MAXB_ * BOX_);
            int r = idx % (MAXB_ * BOX_);
            int j = r / BOX_, c = r % BOX_;
            out[idx] = (j < bc) ? g_box[bc - 1 - j][b * BOX_ + c] : 0.f;
        } else {
            int i2 = idx - NBOX;
            int b = i2 / (MAXSY_ * S_);
            int r = i2 % (MAXSY_ * S_);
            int j = r / S_, c = r % S_;
            out[idx] = (j < sc) ? g_sym[sc - 1 - j][b * S_ + c] : 0.f;
        }
    }
}

extern "C" void kernel_launch(void* const* d_in, const int* in_sizes, int n_in,
                              void* d_out, int out_size) {
    (void)in_sizes; (void)n_in; (void)out_size;
    k_persist<<<G_, NT_>>>(
        (const float*)d_in[0], (const int*)d_in[1],
        (const float*)d_in[2], (const float*)d_in[3],
        (const float*)d_in[4], (const float*)d_in[5],
        (const float*)d_in[6], (const float*)d_in[7],
        (const float*)d_in[8], (const float*)d_in[9],
        (const float*)d_in[10], (const float*)d_in[11],
        (const float*)d_in[12], (const float*)d_in[13],
        (const float*)d_in[14], (const float*)d_in[15],
        (float*)d_out);
}